// round 15
// baseline (speedup 1.0000x reference)
#include <cuda_runtime.h>

// LbpBlock: out = concat([x, pad(x_cat)], ch axis)
//   y[n,o,h,w] = sum_c x[n,c,h,w]*conv_w[o,c]   (c=3, o=64)
//   x_cat interior = sum_l H(y_c - y_shift_l) * exp(w[o,l]), zero border.
// x: (8,3,256,256) f32, conv_w: (64,3), w: (64,8) -> out: (8,67,256,256)
//
// R15: 20 warps/SM via honest liveness reduction. f2 windows (36 regs vs
// 72) with CP=39 (odd) so warp row-quads alternate 64B bank phases
// (conflict degree 2 -> crossbar cycles equal to f4). Halo fill in two
// 3-slot batches (36 live vs 72). launch_bounds(128,5) -> 102 regs,
// 5 CTAs x 4 warps = 20 warps/SM. One barrier per block.

#define NN   8
#define CIN  3
#define HH   256
#define WW   256
#define TH   64                    // tile rows
#define TW   32                    // tile cols
#define NT   128
#define HALO_H 66
#define HALO_W 34
#define CP   39                    // ODD f4 pitch (sw(33)=37 < 39)
#define PLANE (HH * WW)
#define NF4  528                   // interior f4 slots: 66 rows x 8
#define NSLOT (NF4 + 132)          // + scalar edge slots (66 rows x 2)

struct Sm {
    float4 sy[HALO_H][CP];         // 41184 B: y for this block's 4 channels
    float2 sewp[2][8];             // exp(w) for the 2 channel pairs
};                                  // 41312 B -> 5 CTAs/SM (206.6 KB)

__device__ __forceinline__ int sw(int c) { return c + (c >> 3); }

__global__ __launch_bounds__(NT, 5)
void lbp_main(const float* __restrict__ x,
              const float* __restrict__ cw,
              const float* __restrict__ w,
              float* __restrict__ out)
{
    extern __shared__ unsigned char raw[];
    Sm* sm = (Sm*)raw;

    const int tid = threadIdx.x;
    const int bz  = blockIdx.z;
    const int n   = bz >> 4;          // image
    const int cg  = bz & 15;          // channel group (4 ch = 1 chunk)
    const int o0  = 4 * cg;
    const int h0  = blockIdx.y * TH;
    const int w0  = blockIdx.x * TW;

    // ---- exp(w) for this block's 2 channel pairs (16 expf total) ----
    if (tid < 16) {
        const int pi = tid >> 3, l = tid & 7;
        sm->sewp[pi][l] = make_float2(__expf(w[(o0 + 2 * pi) * 8 + l]),
                                      __expf(w[(o0 + 2 * pi + 1) * 8 + l]));
    }

    // ---- conv weights: 3 broadcast LDG.128 (12*cg % 4 == 0 -> aligned) ----
    const float4* cw4 = (const float4*)(cw + 3 * o0);
    const float4 W0 = cw4[0], W1 = cw4[1], W2 = cw4[2];
    // ch0=(W0.x,W0.y,W0.z) ch1=(W0.w,W1.x,W1.y)
    // ch2=(W1.z,W1.w,W2.x) ch3=(W2.y,W2.z,W2.w)

    // ---- distributed copy: every block copies 96 f4 of its tile ----
    if (tid < 96) {
        const float4* x4 = (const float4*)(x + n * CIN * PLANE);
        float4*       o4 = (float4*)(out + n * 67 * PLANE);
        const int f   = cg * 96 + tid;       // 1536 f4 per tile / 16 groups
        const int c   = f >> 9;              // 512 f4 per channel-tile
        const int rem = f & 511;
        const int rr  = rem >> 3;            // 64 rows x 8 f4
        const int cc  = rem & 7;
        const int idx = c * (PLANE / 4) + (h0 + rr) * (WW / 4) + (w0 >> 2) + cc;
        o4[idx] = x4[idx];
    }

    // ---- x halo fill in TWO 3-slot batches (caps liveness at ~45 regs) ----
    // slot s < NF4: interior f4 (row r = s>>3, 4 px at halo col 1+4q)
    // slot s >= NF4: scalar edge (row (s-NF4)>>1, halo col 0 or 33)
    #pragma unroll
    for (int b = 0; b < 2; b++) {
        float xs[3][3][4];            // [k][plane][px]
        int   rk[3], ck[3], tk[3];
        #pragma unroll
        for (int k = 0; k < 3; k++) {
            const int s = tid + (3 * b + k) * NT;
            #pragma unroll
            for (int p = 0; p < 3; p++)
                #pragma unroll
                for (int i = 0; i < 4; i++)
                    xs[k][p][i] = 0.f;
            if (s < NF4) {
                const int r = s >> 3, q = s & 7;
                rk[k] = r; ck[k] = 1 + 4 * q; tk[k] = 0;
                const int gh = h0 - 1 + r;
                if ((unsigned)gh < HH) {
                    const int base = (n * CIN * HH + gh) * WW + (w0 + 4 * q);
                    #pragma unroll
                    for (int p = 0; p < 3; p++) {
                        const float4 t = *(const float4*)(x + base + p * PLANE);
                        xs[k][p][0] = t.x; xs[k][p][1] = t.y;
                        xs[k][p][2] = t.z; xs[k][p][3] = t.w;
                    }
                }
            } else if (s < NSLOT) {
                const int e2 = s - NF4;
                const int r = e2 >> 1, side = e2 & 1;
                rk[k] = r; ck[k] = side ? 33 : 0; tk[k] = 1;
                const int gh = h0 - 1 + r;
                const int gw = w0 - 1 + (side ? 33 : 0);
                if ((unsigned)gh < HH && (unsigned)gw < WW) {
                    const int base = (n * CIN * HH + gh) * WW + gw;
                    #pragma unroll
                    for (int p = 0; p < 3; p++)
                        xs[k][p][0] = x[base + p * PLANE];
                }
            } else {
                rk[k] = 0; ck[k] = 0; tk[k] = 2;
            }
        }
        #pragma unroll
        for (int k = 0; k < 3; k++) {
            if (tk[k] == 0) {
                #pragma unroll
                for (int i = 0; i < 4; i++) {
                    const float a = xs[k][0][i], bb = xs[k][1][i], d = xs[k][2][i];
                    float4 v;
                    v.x = fmaf(d, W0.z, fmaf(bb, W0.y, a * W0.x));
                    v.y = fmaf(d, W1.y, fmaf(bb, W1.x, a * W0.w));
                    v.z = fmaf(d, W2.x, fmaf(bb, W1.w, a * W1.z));
                    v.w = fmaf(d, W2.w, fmaf(bb, W2.z, a * W2.y));
                    sm->sy[rk[k]][sw(ck[k] + i)] = v;
                }
            } else if (tk[k] == 1) {
                const float a = xs[k][0][0], bb = xs[k][1][0], d = xs[k][2][0];
                float4 v;
                v.x = fmaf(d, W0.z, fmaf(bb, W0.y, a * W0.x));
                v.y = fmaf(d, W1.y, fmaf(bb, W1.x, a * W0.w));
                v.z = fmaf(d, W2.x, fmaf(bb, W1.w, a * W1.z));
                v.w = fmaf(d, W2.w, fmaf(bb, W2.z, a * W2.y));
                sm->sy[rk[k]][sw(ck[k])] = v;
            }
        }
    }
    __syncthreads();   // the ONLY barrier (4-warp convoy)

    // ---- phase 2: 4x4 px micro-tile, f2 rolling window, pair-sequential ----
    const int mc  = tid & 7;             // col group (4 px)
    const int mrg = tid >> 3;            // row quad (0..15)
    const int hr0 = 4 * mrg;             // top window halo row
    const int sc0 = 4 * mc;              // window halo col base
    const int oh0 = h0 + 4 * mrg;
    const int owb = w0 + 4 * mc;

    float rm[4], cm[4];
    #pragma unroll
    for (int pr = 0; pr < 4; pr++)
        rm[pr] = ((unsigned)(oh0 + pr - 1) < (unsigned)(HH - 2)) ? 1.f : 0.f;
    #pragma unroll
    for (int jj = 0; jj < 4; jj++)
        cm[jj] = ((unsigned)(owb + jj - 1) < (unsigned)(WW - 2)) ? 1.f : 0.f;

    float* const outB = out + (n * 67 + 3 + o0) * PLANE + owb;

    // f2 half 'p' of the f4 at (row r, halo col c)
    #define LDF2(r, c, p) (((const float2*)&sm->sy[r][sw(c)])[p])
    #define LOADROW2(D, r, p) {                    \
        _Pragma("unroll")                          \
        for (int j = 0; j < 6; j++)                \
            D[j] = LDF2(r, sc0 + j, p);            \
    }

    // DOROW: one pixel row (pr) for channel pair (e[].x -> cA, e[].y -> cA+1)
    #define DOROW(T, M, Bo, pr, cA) {                                     \
        float rA[4], rB[4];                                               \
        _Pragma("unroll")                                                 \
        for (int jj = 0; jj < 4; jj++) {                                  \
            const float2 ce = M[jj + 1];                                  \
            float a0 = 0.f, a1 = 0.f;                                     \
            /* TL, T, TR, L, BL, B, BR, R (reference shift order) */      \
            if (ce.x > T[jj     ].x) a0 += e[0].x;                        \
            if (ce.y > T[jj     ].y) a1 += e[0].y;                        \
            if (ce.x > T[jj + 1 ].x) a0 += e[1].x;                        \
            if (ce.y > T[jj + 1 ].y) a1 += e[1].y;                        \
            if (ce.x > T[jj + 2 ].x) a0 += e[2].x;                        \
            if (ce.y > T[jj + 2 ].y) a1 += e[2].y;                        \
            if (ce.x > M[jj     ].x) a0 += e[3].x;                        \
            if (ce.y > M[jj     ].y) a1 += e[3].y;                        \
            if (ce.x > Bo[jj    ].x) a0 += e[4].x;                        \
            if (ce.y > Bo[jj    ].y) a1 += e[4].y;                        \
            if (ce.x > Bo[jj + 1].x) a0 += e[5].x;                        \
            if (ce.y > Bo[jj + 1].y) a1 += e[5].y;                        \
            if (ce.x > Bo[jj + 2].x) a0 += e[6].x;                        \
            if (ce.y > Bo[jj + 2].y) a1 += e[6].y;                        \
            if (ce.x > M[jj + 2 ].x) a0 += e[7].x;                        \
            if (ce.y > M[jj + 2 ].y) a1 += e[7].y;                        \
            const float m = rm[pr] * cm[jj];                              \
            rA[jj] = a0 * m;                                              \
            rB[jj] = a1 * m;                                              \
        }                                                                 \
        float* op = outB + (cA) * PLANE + (oh0 + (pr)) * WW;              \
        *(float4*)op           = make_float4(rA[0], rA[1], rA[2], rA[3]); \
        *(float4*)(op + PLANE) = make_float4(rB[0], rB[1], rB[2], rB[3]); \
    }

    #pragma unroll
    for (int p = 0; p < 2; p++) {        // channel pair (f2 half of the f4)
        // exp(w) for this pair, hoisted across all 4 rows
        float2 e[8];
        {
            const float4* q4 = (const float4*)&sm->sewp[p][0];
            #pragma unroll
            for (int qq = 0; qq < 4; qq++) {
                const float4 u = q4[qq];
                e[2 * qq]     = make_float2(u.x, u.y);
                e[2 * qq + 1] = make_float2(u.z, u.w);
            }
        }
        const int cA = 2 * p;

        float2 A[6], B[6], C[6];
        LOADROW2(A, hr0,     p)
        LOADROW2(B, hr0 + 1, p)
        LOADROW2(C, hr0 + 2, p)

        DOROW(A, B, C, 0, cA)            // row 0: T=A M=B Bo=C
        LOADROW2(A, hr0 + 3, p)
        DOROW(B, C, A, 1, cA)            // row 1: T=B M=C Bo=A
        LOADROW2(B, hr0 + 4, p)
        DOROW(C, A, B, 2, cA)            // row 2: T=C M=A Bo=B
        LOADROW2(C, hr0 + 5, p)
        DOROW(A, B, C, 3, cA)            // row 3: T=A M=B Bo=C
    }
    #undef DOROW
    #undef LOADROW2
    #undef LDF2
}

extern "C" void kernel_launch(void* const* d_in, const int* in_sizes, int n_in,
                              void* d_out, int out_size)
{
    const float* x  = (const float*)d_in[0];
    const float* cw = (const float*)d_in[1];
    const float* w  = (const float*)d_in[2];
    float* out = (float*)d_out;

    const int smbytes = (int)sizeof(Sm);   // 41312
    cudaFuncSetAttribute(lbp_main, cudaFuncAttributeMaxDynamicSharedMemorySize,
                         smbytes);

    dim3 grid(WW / TW, HH / TH, NN * 16);   // (8, 4, 128) = 4096 blocks
    lbp_main<<<grid, NT, smbytes>>>(x, cw, w, out);
}

// round 16
// speedup vs baseline: 1.1994x; 1.1994x over previous
#include <cuda_runtime.h>

// LbpBlock: out = concat([x, pad(x_cat)], ch axis)
//   y[n,o,h,w] = sum_c x[n,c,h,w]*conv_w[o,c]   (c=3, o=64)
//   x_cat interior = sum_l H(y_c - y_shift_l) * exp(w[o,l]), zero border.
// x: (8,3,256,256) f32, conv_w: (64,3), w: (64,8) -> out: (8,67,256,256)
//
// R16 = R12 engine + shared-edge comparisons: each interior neighbor edge
// is FSETP'd once and applied to both sides via @P/@!P (horizontal edges
// within each pixel row; the 14 middle edges between the thread's two
// pixel rows serve row0's BL/B/BR and row1's TL/T/TR). FSETP per channel
// 64 -> 48 (-25%), ~-10% of total issue, all on the hottest (alu) pipe.

#define NN   8
#define CIN  3
#define HH   256
#define WW   256
#define TH   32
#define TW   64
#define NT   256
#define HALO_H 34
#define HALO_W 66
#define CP   74                    // swizzled f4 row pitch (sw(65)=73)
#define PLANE (HH * WW)
#define NF4  544                   // interior f4 slots: 34 rows x 16
#define NSLOT (NF4 + 68)           // + scalar edge slots (34 rows x 2)

struct Sm {
    float4 sy[2][HALO_H][CP];      // 80512 B: y for both chunks (8 ch)
    float2 sewp[4][8];             // exp(w) for this block's 4 channel pairs
};                                  // 80768 B -> 2 CTAs/SM

__device__ __forceinline__ int sw(int c) { return c + (c >> 3); }

__global__ __launch_bounds__(NT, 2)
void lbp_main(const float* __restrict__ x,
              const float* __restrict__ cw,
              const float* __restrict__ w,
              float* __restrict__ out)
{
    extern __shared__ unsigned char raw[];
    Sm* sm = (Sm*)raw;

    const int tid = threadIdx.x;
    const int bz  = blockIdx.z;
    const int n   = bz >> 3;          // image
    const int cg  = bz & 7;           // channel group (8 ch)
    const int o0  = 8 * cg;
    const int h0  = blockIdx.y * TH;
    const int w0  = blockIdx.x * TW;

    // ---- exp(w) for this block's 4 channel pairs (32 expf total) ----
    if (tid < 32) {
        const int pi = tid >> 3, l = tid & 7;
        sm->sewp[pi][l] = make_float2(__expf(w[(o0 + 2 * pi) * 8 + l]),
                                      __expf(w[(o0 + 2 * pi + 1) * 8 + l]));
    }

    // ---- conv weights: 6 broadcast LDG.128 (24*cg % 4 == 0 -> aligned) ----
    const float4* cw4 = (const float4*)(cw + 3 * o0);
    const float4 A0 = cw4[0], A1 = cw4[1], A2 = cw4[2];   // chunk 0 (4 ch)
    const float4 B0 = cw4[3], B1 = cw4[4], B2 = cw4[5];   // chunk 1 (4 ch)

    // ---- x halo -> registers, shift-only indexing ----
    float xs[3][3][4];                // [k][plane][px]
    int   rk[3], ck[3], tk[3];        // row, first halo col, type
    #pragma unroll
    for (int k = 0; k < 3; k++) {
        const int s = tid + k * NT;
        #pragma unroll
        for (int p = 0; p < 3; p++)
            #pragma unroll
            for (int i = 0; i < 4; i++)
                xs[k][p][i] = 0.f;
        if (s < NF4) {
            const int r = s >> 4, q = s & 15;
            rk[k] = r; ck[k] = 1 + 4 * q; tk[k] = 0;
            const int gh = h0 - 1 + r;
            if ((unsigned)gh < HH) {
                const int base = (n * CIN * HH + gh) * WW + (w0 + 4 * q);
                #pragma unroll
                for (int p = 0; p < 3; p++) {
                    const float4 t = *(const float4*)(x + base + p * PLANE);
                    xs[k][p][0] = t.x; xs[k][p][1] = t.y;
                    xs[k][p][2] = t.z; xs[k][p][3] = t.w;
                }
            }
        } else if (s < NSLOT) {
            const int e2 = s - NF4;
            const int r = e2 >> 1, side = e2 & 1;
            rk[k] = r; ck[k] = side ? 65 : 0; tk[k] = 1;
            const int gh = h0 - 1 + r;
            const int gw = w0 - 1 + ck[k];
            if ((unsigned)gh < HH && (unsigned)gw < WW) {
                const int base = (n * CIN * HH + gh) * WW + gw;
                #pragma unroll
                for (int p = 0; p < 3; p++)
                    xs[k][p][0] = x[base + p * PLANE];
            }
        } else {
            rk[k] = 0; ck[k] = 0; tk[k] = 2;
        }
    }

    // ---- distributed copy: every block copies 192 f4 of its tile ----
    if (tid < 192) {
        const float4* x4 = (const float4*)(x + n * CIN * PLANE);
        float4*       o4 = (float4*)(out + n * 67 * PLANE);
        const int f   = cg * 192 + tid;
        const int c   = f >> 9;
        const int rem = f & 511;
        const int rr  = rem >> 4;
        const int cc  = rem & 15;
        const int idx = c * (PLANE / 4) + (h0 + rr) * (WW / 4) + (w0 >> 2) + cc;
        o4[idx] = x4[idx];
    }

    // ---- fill BOTH chunks' y (register FMA -> STS.128) ----
    #pragma unroll
    for (int ch2 = 0; ch2 < 2; ch2++) {
        const float4 W0 = ch2 ? B0 : A0;
        const float4 W1 = ch2 ? B1 : A1;
        const float4 W2 = ch2 ? B2 : A2;
        #pragma unroll
        for (int k = 0; k < 3; k++) {
            if (tk[k] == 0) {
                #pragma unroll
                for (int i = 0; i < 4; i++) {
                    const float a = xs[k][0][i], b = xs[k][1][i], d = xs[k][2][i];
                    float4 v;
                    v.x = fmaf(d, W0.z, fmaf(b, W0.y, a * W0.x));
                    v.y = fmaf(d, W1.y, fmaf(b, W1.x, a * W0.w));
                    v.z = fmaf(d, W2.x, fmaf(b, W1.w, a * W1.z));
                    v.w = fmaf(d, W2.w, fmaf(b, W2.z, a * W2.y));
                    sm->sy[ch2][rk[k]][sw(ck[k] + i)] = v;
                }
            } else if (tk[k] == 1) {
                const float a = xs[k][0][0], b = xs[k][1][0], d = xs[k][2][0];
                float4 v;
                v.x = fmaf(d, W0.z, fmaf(b, W0.y, a * W0.x));
                v.y = fmaf(d, W1.y, fmaf(b, W1.x, a * W0.w));
                v.z = fmaf(d, W2.x, fmaf(b, W1.w, a * W1.z));
                v.w = fmaf(d, W2.w, fmaf(b, W2.z, a * W2.y));
                sm->sy[ch2][rk[k]][sw(ck[k])] = v;
            }
        }
    }
    __syncthreads();   // the ONLY barrier

    // ---- phase 2: 2 rows x 4 cols micro-tile, shared-edge comparisons ----
    const int mc  = tid & 15;            // col group (4 px)
    const int mrg = tid >> 4;            // row pair (0..15)
    const int hr0 = 2 * mrg;             // top window halo row
    const int sc0 = 4 * mc;              // window halo col base
    const int oh0 = h0 + 2 * mrg;
    const int owb = w0 + 4 * mc;

    float mk0[4], mk1[4];
    {
        const bool hv0 = ((unsigned)(oh0 - 1) < (unsigned)(HH - 2));
        const bool hv1 = ((unsigned)(oh0)     < (unsigned)(HH - 2));
        #pragma unroll
        for (int jj = 0; jj < 4; jj++) {
            const bool cmj = ((unsigned)(owb + jj - 1) < (unsigned)(WW - 2));
            mk0[jj] = (hv0 && cmj) ? 1.f : 0.f;
            mk1[jj] = (hv1 && cmj) ? 1.f : 0.f;
        }
    }
    float* const outB = out + (n * 67 + 3 + o0) * PLANE + owb;

    // ROW0: row0 partial acc = top-halo (l0,l1,l2) + horizontal L/R (l3,l7)
    // via 5 shared edges on M.
    #define ROW0(T, M, FX, FY, ep, tx, ty) {                              \
        const float2 E0 = ep[0], E1 = ep[1], E2 = ep[2];                  \
        const float2 E3 = ep[3], E7 = ep[7];                              \
        _Pragma("unroll")                                                 \
        for (int jj = 0; jj < 4; jj++) {                                  \
            const float cx = M[jj + 1].FX, cy = M[jj + 1].FY;             \
            float ax = (cx > T[jj].FX) ? E0.x : 0.f;                      \
            float ay = (cy > T[jj].FY) ? E0.y : 0.f;                      \
            ax += (cx > T[jj + 1].FX) ? E1.x : 0.f;                       \
            ay += (cy > T[jj + 1].FY) ? E1.y : 0.f;                       \
            ax += (cx > T[jj + 2].FX) ? E2.x : 0.f;                       \
            ay += (cy > T[jj + 2].FY) ? E2.y : 0.f;                       \
            tx[jj] = ax; ty[jj] = ay;                                     \
        }                                                                 \
        _Pragma("unroll")                                                 \
        for (int j = 0; j < 5; j++) {                                     \
            const bool dx = M[j].FX > M[j + 1].FX;                        \
            const bool dy = M[j].FY > M[j + 1].FY;                        \
            if (j >= 1) { tx[j-1] += dx ? E7.x : 0.f;                     \
                          ty[j-1] += dy ? E7.y : 0.f; }                   \
            if (j <= 3) { tx[j]   += dx ? 0.f : E3.x;                     \
                          ty[j]   += dy ? 0.f : E3.y; }                   \
        }                                                                 \
    }

    // ROW1: shared middle edges (M<->C) finish row0 (l4,l5,l6) and start
    // row1 (l0,l1,l2 as complements); then row1 horizontals + bottom halo
    // vs D; masked stores for both rows, both channels of the pair.
    #define ROW1(M, C, D, FX, FY, ep, tx, ty, cA) {                       \
        const float2 E0 = ep[0], E1 = ep[1], E2 = ep[2], E3 = ep[3];      \
        const float2 E4 = ep[4], E5 = ep[5], E6 = ep[6], E7 = ep[7];      \
        float bx[4], by[4];                                               \
        _Pragma("unroll")                                                 \
        for (int k2 = 0; k2 < 4; k2++) { bx[k2] = 0.f; by[k2] = 0.f; }    \
        /* DL edges: M[a+1] vs C[a] -> row0 BL (l4), row1 TR (l2) */      \
        _Pragma("unroll")                                                 \
        for (int a = 0; a < 5; a++) {                                     \
            const bool dx = M[a + 1].FX > C[a].FX;                        \
            const bool dy = M[a + 1].FY > C[a].FY;                        \
            if (a <= 3) { tx[a]   += dx ? E4.x : 0.f;                     \
                          ty[a]   += dy ? E4.y : 0.f; }                   \
            if (a >= 1) { bx[a-1] += dx ? 0.f : E2.x;                     \
                          by[a-1] += dy ? 0.f : E2.y; }                   \
        }                                                                 \
        /* V edges: M[a+1] vs C[a+1] -> row0 B (l5), row1 T (l1) */       \
        _Pragma("unroll")                                                 \
        for (int a = 0; a < 4; a++) {                                     \
            const bool dx = M[a + 1].FX > C[a + 1].FX;                    \
            const bool dy = M[a + 1].FY > C[a + 1].FY;                    \
            tx[a] += dx ? E5.x : 0.f;   ty[a] += dy ? E5.y : 0.f;         \
            bx[a] += dx ? 0.f : E1.x;   by[a] += dy ? 0.f : E1.y;         \
        }                                                                 \
        /* DR edges: M[a] vs C[a+1] -> row0 BR (l6), row1 TL (l0) */      \
        _Pragma("unroll")                                                 \
        for (int a = 0; a < 5; a++) {                                     \
            const bool dx = M[a].FX > C[a + 1].FX;                        \
            const bool dy = M[a].FY > C[a + 1].FY;                        \
            if (a >= 1) { tx[a-1] += dx ? E6.x : 0.f;                     \
                          ty[a-1] += dy ? E6.y : 0.f; }                   \
            if (a <= 3) { bx[a]   += dx ? 0.f : E0.x;                     \
                          by[a]   += dy ? 0.f : E0.y; }                   \
        }                                                                 \
        /* row1 horizontal edges on C (l3, l7) */                         \
        _Pragma("unroll")                                                 \
        for (int j = 0; j < 5; j++) {                                     \
            const bool dx = C[j].FX > C[j + 1].FX;                        \
            const bool dy = C[j].FY > C[j + 1].FY;                        \
            if (j >= 1) { bx[j-1] += dx ? E7.x : 0.f;                     \
                          by[j-1] += dy ? E7.y : 0.f; }                   \
            if (j <= 3) { bx[j]   += dx ? 0.f : E3.x;                     \
                          by[j]   += dy ? 0.f : E3.y; }                   \
        }                                                                 \
        /* bottom halo: row1 l4,l5,l6 vs D */                             \
        _Pragma("unroll")                                                 \
        for (int jj = 0; jj < 4; jj++) {                                  \
            const float cx = C[jj + 1].FX, cy = C[jj + 1].FY;             \
            bx[jj] += (cx > D[jj].FX)     ? E4.x : 0.f;                   \
            by[jj] += (cy > D[jj].FY)     ? E4.y : 0.f;                   \
            bx[jj] += (cx > D[jj + 1].FX) ? E5.x : 0.f;                   \
            by[jj] += (cy > D[jj + 1].FY) ? E5.y : 0.f;                   \
            bx[jj] += (cx > D[jj + 2].FX) ? E6.x : 0.f;                   \
            by[jj] += (cy > D[jj + 2].FY) ? E6.y : 0.f;                   \
        }                                                                 \
        float* op0 = outB + (cA) * PLANE + oh0 * WW;                      \
        float* op1 = op0 + WW;                                            \
        *(float4*)op0 = make_float4(tx[0] * mk0[0], tx[1] * mk0[1],       \
                                    tx[2] * mk0[2], tx[3] * mk0[3]);      \
        *(float4*)(op0 + PLANE) = make_float4(                            \
            ty[0] * mk0[0], ty[1] * mk0[1],                               \
            ty[2] * mk0[2], ty[3] * mk0[3]);                              \
        *(float4*)op1 = make_float4(bx[0] * mk1[0], bx[1] * mk1[1],       \
                                    bx[2] * mk1[2], bx[3] * mk1[3]);      \
        *(float4*)(op1 + PLANE) = make_float4(                            \
            by[0] * mk1[0], by[1] * mk1[1],                               \
            by[2] * mk1[2], by[3] * mk1[3]);                              \
    }

    #pragma unroll
    for (int ch2 = 0; ch2 < 2; ch2++) {
        float4 (*cur)[CP] = sm->sy[ch2];

        float4 A[6], Bw[6], Cw[6];
        #pragma unroll
        for (int j = 0; j < 6; j++) {
            A[j]  = cur[hr0    ][sw(sc0 + j)];
            Bw[j] = cur[hr0 + 1][sw(sc0 + j)];
            Cw[j] = cur[hr0 + 2][sw(sc0 + j)];
        }

        float t1x[4], t1y[4], t2x[4], t2y[4];
        {
            const float2* ep = sm->sewp[2 * ch2];
            ROW0(A, Bw, x, y, ep, t1x, t1y)
        }
        {
            const float2* ep = sm->sewp[2 * ch2 + 1];
            ROW0(A, Bw, z, w, ep, t2x, t2y)
        }

        // roll: A now holds the row below row1 (D)
        #pragma unroll
        for (int j = 0; j < 6; j++)
            A[j] = cur[hr0 + 3][sw(sc0 + j)];

        {
            const float2* ep = sm->sewp[2 * ch2];
            ROW1(Bw, Cw, A, x, y, ep, t1x, t1y, 4 * ch2)
        }
        {
            const float2* ep = sm->sewp[2 * ch2 + 1];
            ROW1(Bw, Cw, A, z, w, ep, t2x, t2y, 4 * ch2 + 2)
        }
    }
    #undef ROW0
    #undef ROW1
}

extern "C" void kernel_launch(void* const* d_in, const int* in_sizes, int n_in,
                              void* d_out, int out_size)
{
    const float* x  = (const float*)d_in[0];
    const float* cw = (const float*)d_in[1];
    const float* w  = (const float*)d_in[2];
    float* out = (float*)d_out;

    const int smbytes = (int)sizeof(Sm);   // 80768
    cudaFuncSetAttribute(lbp_main, cudaFuncAttributeMaxDynamicSharedMemorySize,
                         smbytes);

    dim3 grid(WW / TW, HH / TH, NN * 8);   // (4, 8, 64) = 2048 blocks
    lbp_main<<<grid, NT, smbytes>>>(x, cw, w, out);
}